// round 5
// baseline (speedup 1.0000x reference)
#include <cuda_runtime.h>
#include <cuda_bf16.h>
#include <cstdint>

// ---------------------------------------------------------------------------
// 2-layer GCN:
//   deg[i] = 1 + #incoming edges;  dinv = rsqrt(deg)
//   layer(x, W, b):  h' = dinv ⊙ (x @ W)
//                    agg[i] = h'[i] (self loop) + sum_{e: dst=i} h'[src(e)]
//                    out = relu(dinv ⊙ agg + b)
// Scratch lives in __device__ globals (no allocation).
// edge_index is int32 (JAX default config downgrades int64 -> int32).
// ---------------------------------------------------------------------------

#define NN 100000
#define NE 1600000

__device__ __align__(128) float g_deg [NN];
__device__ __align__(128) float g_dinv[NN];
__device__ __align__(128) float g_bufA[(size_t)NN * 128];  // gather source
__device__ __align__(128) float g_bufB[(size_t)NN * 128];  // accumulator

// ---------------------------------------------------------------- small ones
__global__ void init_deg_kernel(float* __restrict__ deg, int n) {
    int i = blockIdx.x * blockDim.x + threadIdx.x;
    if (i < n) deg[i] = 1.0f;  // self loop
}

__global__ void deg_edges_kernel(const int* __restrict__ dst,
                                 float* __restrict__ deg, int e) {
    int i = blockIdx.x * blockDim.x + threadIdx.x;
    if (i < e) atomicAdd(&deg[dst[i]], 1.0f);
}

__global__ void dinv_kernel(const float* __restrict__ deg,
                            float* __restrict__ dinv, int n) {
    int i = blockIdx.x * blockDim.x + threadIdx.x;
    if (i < n) dinv[i] = rsqrtf(deg[i]);   // deg >= 1 always
}

// --------------------------------------------------------------------- GEMM
// out1[m][c] = out2[m][c] = dinv[m] * sum_k X[m][k] * W[k][c]
// BM=64, K=128 fixed, BN in {128, 64}. 256 threads, 4x(BN/16) micro-tile.
template <int BN>
__global__ __launch_bounds__(256)
void gemm_scale_kernel(const float* __restrict__ X, const float* __restrict__ W,
                       const float* __restrict__ dinv,
                       float* __restrict__ out1, float* __restrict__ out2, int M) {
    constexpr int K  = 128;
    constexpr int BM = 64;
    constexpr int TN = BN / 16;          // 8 or 4
    constexpr int XS = K + 4;            // padded row stride (floats)

    extern __shared__ float smem[];
    float* Xs = smem;                    // BM * XS
    float* Ws = smem + BM * XS;          // K * BN

    const int tid       = threadIdx.x;
    const int block_row = blockIdx.x * BM;

    // stage W (K x BN, row-major, contiguous)
    {
        const float4* W4  = (const float4*)W;
        float4*       Ws4 = (float4*)Ws;
        for (int i = tid; i < K * BN / 4; i += 256) Ws4[i] = W4[i];
    }
    // stage X tile (BM x K) with padded rows
    {
        const float4* X4  = (const float4*)X;
        float4*       Xs4 = (float4*)Xs;            // row stride XS/4 = 33
        for (int i = tid; i < BM * (K / 4); i += 256) {
            int r = i >> 5;                          // / 32
            int c = i & 31;
            int gr = block_row + r;
            float4 v = make_float4(0.f, 0.f, 0.f, 0.f);
            if (gr < M) v = X4[(size_t)gr * (K / 4) + c];
            Xs4[r * (XS / 4) + c] = v;
        }
    }
    __syncthreads();

    const int tx = tid & 15;   // col group
    const int ty = tid >> 4;   // row group

    float acc[4][TN];
#pragma unroll
    for (int i = 0; i < 4; i++)
#pragma unroll
        for (int j = 0; j < TN; j++) acc[i][j] = 0.f;

    const float4* Ws4 = (const float4*)Ws;
#pragma unroll 8
    for (int k = 0; k < K; k++) {
        float xr[4];
#pragma unroll
        for (int i = 0; i < 4; i++) xr[i] = Xs[(ty * 4 + i) * XS + k];
        float4 w[TN / 4];
#pragma unroll
        for (int j = 0; j < TN / 4; j++)
            w[j] = Ws4[k * (BN / 4) + tx * (TN / 4) + j];
#pragma unroll
        for (int i = 0; i < 4; i++) {
#pragma unroll
            for (int j = 0; j < TN / 4; j++) {
                acc[i][4 * j + 0] += xr[i] * w[j].x;
                acc[i][4 * j + 1] += xr[i] * w[j].y;
                acc[i][4 * j + 2] += xr[i] * w[j].z;
                acc[i][4 * j + 3] += xr[i] * w[j].w;
            }
        }
    }

#pragma unroll
    for (int i = 0; i < 4; i++) {
        int row = block_row + ty * 4 + i;
        if (row < M) {
            float dv = dinv[row];
#pragma unroll
            for (int j = 0; j < TN / 4; j++) {
                float4 o;
                o.x = acc[i][4 * j + 0] * dv;
                o.y = acc[i][4 * j + 1] * dv;
                o.z = acc[i][4 * j + 2] * dv;
                o.w = acc[i][4 * j + 3] * dv;
                size_t off = (size_t)row * (BN / 4) + tx * (TN / 4) + j;
                ((float4*)out1)[off] = o;
                ((float4*)out2)[off] = o;   // accumulator init = self-loop term
            }
        }
    }
}

// --------------------------------------------------------------- aggregation
// Scalar atomicAdd with unused return -> ptxas emits RED.E.ADD.F32.

// 128 channels: one warp per edge, float4 per lane
__global__ void agg128_kernel(const int* __restrict__ src,
                              const int* __restrict__ dst,
                              const float* __restrict__ A,
                              float* __restrict__ B, int E) {
    int idx  = blockIdx.x * blockDim.x + threadIdx.x;
    int e    = idx >> 5;
    int lane = idx & 31;
    if (e >= E) return;
    int s = src[e];
    int d = dst[e];
    float4 v = ((const float4*)A)[(size_t)s * 32 + lane];
    float* p = B + (size_t)d * 128 + lane * 4;
    atomicAdd(p + 0, v.x);
    atomicAdd(p + 1, v.y);
    atomicAdd(p + 2, v.z);
    atomicAdd(p + 3, v.w);
}

// 64 channels: half-warp per edge
__global__ void agg64_kernel(const int* __restrict__ src,
                             const int* __restrict__ dst,
                             const float* __restrict__ A,
                             float* __restrict__ B, int E) {
    int idx = blockIdx.x * blockDim.x + threadIdx.x;
    int e   = idx >> 4;
    int l   = idx & 15;
    if (e >= E) return;
    int s = src[e];
    int d = dst[e];
    float4 v = ((const float4*)A)[(size_t)s * 16 + l];
    float* p = B + (size_t)d * 64 + l * 4;
    atomicAdd(p + 0, v.x);
    atomicAdd(p + 1, v.y);
    atomicAdd(p + 2, v.z);
    atomicAdd(p + 3, v.w);
}

// ----------------------------------------------------------------- epilogue
// out[row][c] = relu(dinv[row]*agg[row][c] + bias[c]); vectorized by float4.
// shift: log2(C/4) (5 for C=128, 4 for C=64). total = M * (C/4).
__global__ void epilogue_kernel(const float* __restrict__ agg,
                                const float* __restrict__ dinv,
                                const float* __restrict__ bias,
                                float* __restrict__ out, int total, int shift) {
    int idx = blockIdx.x * blockDim.x + threadIdx.x;
    if (idx >= total) return;
    int row = idx >> shift;
    int c   = idx & ((1 << shift) - 1);
    float4 v  = ((const float4*)agg)[idx];
    float4 b  = ((const float4*)bias)[c];
    float  dv = dinv[row];
    v.x = fmaxf(fmaf(v.x, dv, b.x), 0.f);
    v.y = fmaxf(fmaf(v.y, dv, b.y), 0.f);
    v.z = fmaxf(fmaf(v.z, dv, b.z), 0.f);
    v.w = fmaxf(fmaf(v.w, dv, b.w), 0.f);
    ((float4*)out)[idx] = v;
}

// -------------------------------------------------------------------- launch
extern "C" void kernel_launch(void* const* d_in, const int* in_sizes, int n_in,
                              void* d_out, int out_size) {
    const float* x   = (const float*)d_in[0];
    const int*   ei  = (const int*)d_in[1];     // int32 (JAX x64 disabled)
    const float* W1  = (const float*)d_in[2];
    const float* b1  = (const float*)d_in[3];
    const float* W2  = (const float*)d_in[4];
    const float* b2  = (const float*)d_in[5];
    float*       out = (float*)d_out;

    const int N = in_sizes[0] / 128;
    const int E = in_sizes[1] / 2;
    const int* esrc = ei;
    const int* edst = ei + E;

    float *deg, *dinv, *bufA, *bufB;
    cudaGetSymbolAddress((void**)&deg,  g_deg);
    cudaGetSymbolAddress((void**)&dinv, g_dinv);
    cudaGetSymbolAddress((void**)&bufA, g_bufA);
    cudaGetSymbolAddress((void**)&bufB, g_bufB);

    constexpr int SMEM1 = (64 * 132 + 128 * 128) * 4;  // 99328
    constexpr int SMEM2 = (64 * 132 + 128 * 64) * 4;   // 66560
    cudaFuncSetAttribute(gemm_scale_kernel<128>,
                         cudaFuncAttributeMaxDynamicSharedMemorySize, SMEM1);
    cudaFuncSetAttribute(gemm_scale_kernel<64>,
                         cudaFuncAttributeMaxDynamicSharedMemorySize, SMEM2);

    // degree + dinv
    init_deg_kernel<<<(N + 255) / 256, 256>>>(deg, N);
    deg_edges_kernel<<<(E + 255) / 256, 256>>>(edst, deg, E);
    dinv_kernel<<<(N + 255) / 256, 256>>>(deg, dinv, N);

    // layer 1: h' = dinv*(x@W1) -> bufA (gather src) and bufB (accumulator)
    gemm_scale_kernel<128><<<(N + 63) / 64, 256, SMEM1>>>(x, W1, dinv, bufA, bufB, N);
    {
        long long threads = (long long)E * 32;
        agg128_kernel<<<(unsigned)((threads + 255) / 256), 256>>>(esrc, edst, bufA, bufB, E);
    }
    epilogue_kernel<<<(N * 32 + 255) / 256, 256>>>(bufB, dinv, b1, bufA, N * 32, 5);

    // layer 2: h2' = dinv*(h1@W2) -> bufB (gather src, 64 wide) and d_out (accum)
    gemm_scale_kernel<64><<<(N + 63) / 64, 256, SMEM2>>>(bufA, W2, dinv, bufB, out, N);
    {
        long long threads = (long long)E * 16;
        agg64_kernel<<<(unsigned)((threads + 255) / 256), 256>>>(esrc, edst, bufB, out, E);
    }
    epilogue_kernel<<<(N * 16 + 255) / 256, 256>>>(out, dinv, b2, out, N * 16, 4);
}

// round 6
// speedup vs baseline: 3.2999x; 3.2999x over previous
#include <cuda_runtime.h>
#include <cuda_bf16.h>
#include <cstdint>

// ---------------------------------------------------------------------------
// 2-layer GCN, CSR-by-dst gather formulation:
//   deg[i] = 1 + in_degree(i);  dinv = rsqrt(deg)
//   h' = dinv ⊙ (X @ W)                         (GEMM, scaled write)
//   out[d] = relu(dinv[d] * (h'[d] + sum_{s in nbr(d)} h'[s]) + b)   (gather)
// CSR built once per call (counting sort), reused by both layers.
// ---------------------------------------------------------------------------

#define NN 100000
#define NE 1600000

__device__ __align__(128) float g_bufA[(size_t)NN * 128];
__device__ __align__(128) float g_bufB[(size_t)NN * 128];
__device__ __align__(128) float g_dinv[NN];
__device__ __align__(128) int   g_degc[NN];
__device__ __align__(128) int   g_rows[NN + 1];
__device__ __align__(128) int   g_curs[NN];
__device__ __align__(128) int   g_csr [NE];

// ------------------------------------------------------------------ CSR build
__global__ void zero_int_kernel(int* __restrict__ p, int n) {
    int i = blockIdx.x * blockDim.x + threadIdx.x;
    if (i < n) p[i] = 0;
}

__global__ void count_kernel(const int* __restrict__ dst, int* __restrict__ cnt, int e) {
    int i = blockIdx.x * blockDim.x + threadIdx.x;
    if (i < e) atomicAdd(&cnt[dst[i]], 1);
}

__global__ void dinv_kernel(const int* __restrict__ cnt, float* __restrict__ dinv, int n) {
    int i = blockIdx.x * blockDim.x + threadIdx.x;
    if (i < n) dinv[i] = rsqrtf((float)(1 + cnt[i]));
}

// single-block exclusive scan (1024 threads, shfl + smem two-level)
__global__ __launch_bounds__(1024)
void scan_kernel(const int* __restrict__ deg, int* __restrict__ row_start,
                 int* __restrict__ cursor, int n) {
    __shared__ int wsum[32];
    __shared__ int tile_total;
    const int tid = threadIdx.x, lane = tid & 31, wid = tid >> 5;
    int carry = 0;
    for (int base = 0; base < n; base += 1024) {
        int i = base + tid;
        int v = (i < n) ? deg[i] : 0;
        int x = v;
#pragma unroll
        for (int d = 1; d < 32; d <<= 1) {
            int y = __shfl_up_sync(0xffffffffu, x, d);
            if (lane >= d) x += y;
        }
        if (lane == 31) wsum[wid] = x;
        __syncthreads();
        if (wid == 0) {
            int s = wsum[lane];
#pragma unroll
            for (int d = 1; d < 32; d <<= 1) {
                int y = __shfl_up_sync(0xffffffffu, s, d);
                if (lane >= d) s += y;
            }
            wsum[lane] = s;
            if (lane == 31) tile_total = s;
        }
        __syncthreads();
        int excl = carry + (x - v) + (wid > 0 ? wsum[wid - 1] : 0);
        if (i < n) { row_start[i] = excl; cursor[i] = excl; }
        carry += tile_total;
        __syncthreads();
    }
    if (tid == 0) row_start[n] = carry;
}

__global__ void place_kernel(const int* __restrict__ src, const int* __restrict__ dst,
                             int* __restrict__ cursor, int* __restrict__ csr_src, int e) {
    int i = blockIdx.x * blockDim.x + threadIdx.x;
    if (i < e) {
        int pos = atomicAdd(&cursor[dst[i]], 1);
        csr_src[pos] = src[i];
    }
}

// --------------------------------------------------------------------- GEMM
// out[m][c] = dinv[m] * sum_k X[m][k] * W[k][c].  BM=128, K=128, 256 threads,
// 8x(BN/16) micro-tile (64 FMA per ~10 LDS for BN=128).
template <int BN>
__global__ __launch_bounds__(256)
void gemm_scale_kernel(const float* __restrict__ X, const float* __restrict__ W,
                       const float* __restrict__ dinv,
                       float* __restrict__ out, int M) {
    constexpr int K  = 128;
    constexpr int BM = 128;
    constexpr int TN = BN / 16;          // 8 or 4
    constexpr int XS = K + 4;

    extern __shared__ float smem[];
    float* Xs = smem;                    // BM * XS
    float* Ws = smem + BM * XS;          // K * BN

    const int tid       = threadIdx.x;
    const int block_row = blockIdx.x * BM;

    {   // stage W
        const float4* W4  = (const float4*)W;
        float4*       Ws4 = (float4*)Ws;
        for (int i = tid; i < K * BN / 4; i += 256) Ws4[i] = W4[i];
    }
    {   // stage X tile (row-major, padded)
        const float4* X4  = (const float4*)X;
        float4*       Xs4 = (float4*)Xs;            // row stride XS/4 = 33
        for (int i = tid; i < BM * (K / 4); i += 256) {
            int r = i >> 5;
            int c = i & 31;
            int gr = block_row + r;
            float4 v = make_float4(0.f, 0.f, 0.f, 0.f);
            if (gr < M) v = X4[(size_t)gr * (K / 4) + c];
            Xs4[r * (XS / 4) + c] = v;
        }
    }
    __syncthreads();

    const int tx = tid & 15;
    const int ty = tid >> 4;

    float acc[8][TN];
#pragma unroll
    for (int i = 0; i < 8; i++)
#pragma unroll
        for (int j = 0; j < TN; j++) acc[i][j] = 0.f;

    const float4* Ws4 = (const float4*)Ws;
#pragma unroll 4
    for (int k = 0; k < K; k++) {
        float xr[8];
#pragma unroll
        for (int i = 0; i < 8; i++) xr[i] = Xs[(ty * 8 + i) * XS + k];
        float4 w[TN / 4];
#pragma unroll
        for (int j = 0; j < TN / 4; j++)
            w[j] = Ws4[k * (BN / 4) + tx * (TN / 4) + j];
#pragma unroll
        for (int i = 0; i < 8; i++) {
#pragma unroll
            for (int j = 0; j < TN / 4; j++) {
                acc[i][4 * j + 0] += xr[i] * w[j].x;
                acc[i][4 * j + 1] += xr[i] * w[j].y;
                acc[i][4 * j + 2] += xr[i] * w[j].z;
                acc[i][4 * j + 3] += xr[i] * w[j].w;
            }
        }
    }

#pragma unroll
    for (int i = 0; i < 8; i++) {
        int row = block_row + ty * 8 + i;
        if (row < M) {
            float dv = dinv[row];
#pragma unroll
            for (int j = 0; j < TN / 4; j++) {
                float4 o;
                o.x = acc[i][4 * j + 0] * dv;
                o.y = acc[i][4 * j + 1] * dv;
                o.z = acc[i][4 * j + 2] * dv;
                o.w = acc[i][4 * j + 3] * dv;
                ((float4*)out)[(size_t)row * (BN / 4) + tx * (TN / 4) + j] = o;
            }
        }
    }
}

// -------------------------------------------------- gather + fused epilogue
// 128 channels: warp per dst, lane holds float4 (4 channels).
__global__ void gather128_kernel(const float* __restrict__ A,
                                 const int* __restrict__ row_start,
                                 const int* __restrict__ csr_src,
                                 const float* __restrict__ dinv,
                                 const float* __restrict__ bias,
                                 float* __restrict__ out, int N) {
    int idx  = blockIdx.x * blockDim.x + threadIdx.x;
    int d    = idx >> 5;
    int lane = idx & 31;
    if (d >= N) return;
    const float4* A4 = (const float4*)A;
    float4 acc = A4[(size_t)d * 32 + lane];          // self loop
    int rs = row_start[d], re = row_start[d + 1];
    int j = rs;
    for (; j + 1 < re; j += 2) {
        int s0 = csr_src[j], s1 = csr_src[j + 1];
        float4 v0 = A4[(size_t)s0 * 32 + lane];
        float4 v1 = A4[(size_t)s1 * 32 + lane];
        acc.x += v0.x; acc.y += v0.y; acc.z += v0.z; acc.w += v0.w;
        acc.x += v1.x; acc.y += v1.y; acc.z += v1.z; acc.w += v1.w;
    }
    if (j < re) {
        float4 v = A4[(size_t)csr_src[j] * 32 + lane];
        acc.x += v.x; acc.y += v.y; acc.z += v.z; acc.w += v.w;
    }
    float  dv = dinv[d];
    float4 b  = ((const float4*)bias)[lane];
    float4 o;
    o.x = fmaxf(fmaf(acc.x, dv, b.x), 0.f);
    o.y = fmaxf(fmaf(acc.y, dv, b.y), 0.f);
    o.z = fmaxf(fmaf(acc.z, dv, b.z), 0.f);
    o.w = fmaxf(fmaf(acc.w, dv, b.w), 0.f);
    ((float4*)out)[(size_t)d * 32 + lane] = o;
}

// 64 channels: warp per dst, lane holds float2.
__global__ void gather64_kernel(const float* __restrict__ A,
                                const int* __restrict__ row_start,
                                const int* __restrict__ csr_src,
                                const float* __restrict__ dinv,
                                const float* __restrict__ bias,
                                float* __restrict__ out, int N) {
    int idx  = blockIdx.x * blockDim.x + threadIdx.x;
    int d    = idx >> 5;
    int lane = idx & 31;
    if (d >= N) return;
    const float2* A2 = (const float2*)A;
    float2 acc = A2[(size_t)d * 32 + lane];          // self loop
    int rs = row_start[d], re = row_start[d + 1];
    int j = rs;
    for (; j + 1 < re; j += 2) {
        int s0 = csr_src[j], s1 = csr_src[j + 1];
        float2 v0 = A2[(size_t)s0 * 32 + lane];
        float2 v1 = A2[(size_t)s1 * 32 + lane];
        acc.x += v0.x; acc.y += v0.y;
        acc.x += v1.x; acc.y += v1.y;
    }
    if (j < re) {
        float2 v = A2[(size_t)csr_src[j] * 32 + lane];
        acc.x += v.x; acc.y += v.y;
    }
    float  dv = dinv[d];
    float2 b  = ((const float2*)bias)[lane];
    float2 o;
    o.x = fmaxf(fmaf(acc.x, dv, b.x), 0.f);
    o.y = fmaxf(fmaf(acc.y, dv, b.y), 0.f);
    ((float2*)out)[(size_t)d * 32 + lane] = o;
}

// -------------------------------------------------------------------- launch
extern "C" void kernel_launch(void* const* d_in, const int* in_sizes, int n_in,
                              void* d_out, int out_size) {
    const float* x   = (const float*)d_in[0];
    const int*   ei  = (const int*)d_in[1];     // int32 (JAX x64 disabled)
    const float* W1  = (const float*)d_in[2];
    const float* b1  = (const float*)d_in[3];
    const float* W2  = (const float*)d_in[4];
    const float* b2  = (const float*)d_in[5];
    float*       out = (float*)d_out;

    const int N = in_sizes[0] / 128;
    const int E = in_sizes[1] / 2;
    const int* esrc = ei;
    const int* edst = ei + E;

    float *bufA, *bufB, *dinv;
    int *degc, *rows, *curs, *csr;
    cudaGetSymbolAddress((void**)&bufA, g_bufA);
    cudaGetSymbolAddress((void**)&bufB, g_bufB);
    cudaGetSymbolAddress((void**)&dinv, g_dinv);
    cudaGetSymbolAddress((void**)&degc, g_degc);
    cudaGetSymbolAddress((void**)&rows, g_rows);
    cudaGetSymbolAddress((void**)&curs, g_curs);
    cudaGetSymbolAddress((void**)&csr,  g_csr);

    constexpr int SMEM1 = (128 * 132 + 128 * 128) * 4;  // 133120
    constexpr int SMEM2 = (128 * 132 + 128 * 64) * 4;   // 100352
    cudaFuncSetAttribute(gemm_scale_kernel<128>,
                         cudaFuncAttributeMaxDynamicSharedMemorySize, SMEM1);
    cudaFuncSetAttribute(gemm_scale_kernel<64>,
                         cudaFuncAttributeMaxDynamicSharedMemorySize, SMEM2);

    // ---- CSR build (reused by both layers) + dinv
    zero_int_kernel<<<(N + 255) / 256, 256>>>(degc, N);
    count_kernel<<<(E + 255) / 256, 256>>>(edst, degc, E);
    dinv_kernel<<<(N + 255) / 256, 256>>>(degc, dinv, N);
    scan_kernel<<<1, 1024>>>(degc, rows, curs, N);
    place_kernel<<<(E + 255) / 256, 256>>>(esrc, edst, curs, csr, E);

    // ---- layer 1
    gemm_scale_kernel<128><<<(N + 127) / 128, 256, SMEM1>>>(x, W1, dinv, bufA, N);
    {
        long long t = (long long)N * 32;
        gather128_kernel<<<(unsigned)((t + 255) / 256), 256>>>(bufA, rows, csr, dinv, b1, bufB, N);
    }

    // ---- layer 2
    gemm_scale_kernel<64><<<(N + 127) / 128, 256, SMEM2>>>(bufB, W2, dinv, bufA, N);
    {
        long long t = (long long)N * 32;
        gather64_kernel<<<(unsigned)((t + 255) / 256), 256>>>(bufA, rows, csr, dinv, b2, out, N);
    }
}

// round 7
// speedup vs baseline: 3.7097x; 1.1242x over previous
#include <cuda_runtime.h>
#include <cuda_bf16.h>
#include <cstdint>

// ---------------------------------------------------------------------------
// 2-layer GCN, CSR-by-dst gather formulation:
//   deg[i] = 1 + in_degree(i);  dinv = rsqrt(deg)
//   h' = dinv ⊙ (X @ W)                         (GEMM, scaled write)
//   out[d] = relu(dinv[d] * (h'[d] + sum_{s in nbr(d)} h'[s]) + b)   (gather)
// CSR built once per call (counting sort, multi-block scan), reused by both
// layers.
// ---------------------------------------------------------------------------

#define NN 100000
#define NE 1600000

__device__ __align__(128) float g_bufA[(size_t)NN * 128];
__device__ __align__(128) float g_bufB[(size_t)NN * 128];
__device__ __align__(128) float g_dinv[NN];
__device__ __align__(128) int   g_degc[NN];
__device__ __align__(128) int   g_rows[NN + 1];
__device__ __align__(128) int   g_curs[NN];
__device__ __align__(128) int   g_csr [NE];
__device__ __align__(128) int   g_bsum[256];   // per-block totals (<=98 used)
__device__ __align__(128) int   g_boff[256];   // exclusive block offsets

// ------------------------------------------------------------------ CSR build
__global__ void zero_int_kernel(int* __restrict__ p, int n) {
    int i = blockIdx.x * blockDim.x + threadIdx.x;
    if (i < n) p[i] = 0;
}

__global__ void count_kernel(const int* __restrict__ dst, int* __restrict__ cnt, int e) {
    int i = blockIdx.x * blockDim.x + threadIdx.x;
    if (i < e) atomicAdd(&cnt[dst[i]], 1);
}

__global__ void dinv_kernel(const int* __restrict__ cnt, float* __restrict__ dinv, int n) {
    int i = blockIdx.x * blockDim.x + threadIdx.x;
    if (i < n) dinv[i] = rsqrtf((float)(1 + cnt[i]));
}

// pass 1: per-block exclusive scan of deg; local prefix -> row_start,
// block total -> bsum[blockIdx].
__global__ __launch_bounds__(1024)
void scan_local_kernel(const int* __restrict__ deg, int* __restrict__ row_start,
                       int* __restrict__ bsum, int n) {
    __shared__ int wsum[32];
    const int tid = threadIdx.x, lane = tid & 31, wid = tid >> 5;
    const int i = blockIdx.x * 1024 + tid;
    int v = (i < n) ? deg[i] : 0;
    int x = v;
#pragma unroll
    for (int d = 1; d < 32; d <<= 1) {
        int y = __shfl_up_sync(0xffffffffu, x, d);
        if (lane >= d) x += y;
    }
    if (lane == 31) wsum[wid] = x;
    __syncthreads();
    if (wid == 0) {
        int s = wsum[lane];
#pragma unroll
        for (int d = 1; d < 32; d <<= 1) {
            int y = __shfl_up_sync(0xffffffffu, s, d);
            if (lane >= d) s += y;
        }
        wsum[lane] = s;
    }
    __syncthreads();
    int excl = (x - v) + (wid > 0 ? wsum[wid - 1] : 0);
    if (i < n) row_start[i] = excl;
    if (tid == 1023) bsum[blockIdx.x] = excl + v;
}

// pass 2: one block scans the block totals (exclusive); writes rows[n]=total.
__global__ __launch_bounds__(128)
void scan_block_kernel(const int* __restrict__ bsum, int* __restrict__ boff,
                       int* __restrict__ row_start, int nb, int n) {
    __shared__ int carry_s;
    const int tid = threadIdx.x, lane = tid & 31;
    if (tid == 0) carry_s = 0;
    __syncthreads();
    for (int base = 0; base < nb; base += 32) {
        if (tid < 32) {
            int j = base + lane;
            int v = (j < nb) ? bsum[j] : 0;
            int x = v;
#pragma unroll
            for (int d = 1; d < 32; d <<= 1) {
                int y = __shfl_up_sync(0xffffffffu, x, d);
                if (lane >= d) x += y;
            }
            int carry = carry_s;
            if (j < nb) boff[j] = carry + (x - v);
            if (lane == 31) carry_s = carry + x;
        }
        __syncthreads();
    }
    if (tid == 0) row_start[n] = carry_s;
}

// pass 3: add block offsets; write final row_start and cursor.
__global__ __launch_bounds__(1024)
void scan_add_kernel(int* __restrict__ row_start, int* __restrict__ cursor,
                     const int* __restrict__ boff, int n) {
    int i = blockIdx.x * 1024 + threadIdx.x;
    if (i < n) {
        int v = row_start[i] + boff[blockIdx.x];
        row_start[i] = v;
        cursor[i]    = v;
    }
}

__global__ void place_kernel(const int* __restrict__ src, const int* __restrict__ dst,
                             int* __restrict__ cursor, int* __restrict__ csr_src, int e) {
    int i = blockIdx.x * blockDim.x + threadIdx.x;
    if (i < e) {
        int pos = atomicAdd(&cursor[dst[i]], 1);
        csr_src[pos] = src[i];
    }
}

// --------------------------------------------------------------------- GEMM
// out[m][c] = dinv[m] * sum_k X[m][k] * W[k][c].  BM=128, K=128, 256 threads,
// 8x(BN/16) micro-tile.
template <int BN>
__global__ __launch_bounds__(256)
void gemm_scale_kernel(const float* __restrict__ X, const float* __restrict__ W,
                       const float* __restrict__ dinv,
                       float* __restrict__ out, int M) {
    constexpr int K  = 128;
    constexpr int BM = 128;
    constexpr int TN = BN / 16;          // 8 or 4
    constexpr int XS = K + 4;

    extern __shared__ float smem[];
    float* Xs = smem;                    // BM * XS
    float* Ws = smem + BM * XS;          // K * BN

    const int tid       = threadIdx.x;
    const int block_row = blockIdx.x * BM;

    {   // stage W
        const float4* W4  = (const float4*)W;
        float4*       Ws4 = (float4*)Ws;
        for (int i = tid; i < K * BN / 4; i += 256) Ws4[i] = W4[i];
    }
    {   // stage X tile (row-major, padded)
        const float4* X4  = (const float4*)X;
        float4*       Xs4 = (float4*)Xs;            // row stride XS/4 = 33
        for (int i = tid; i < BM * (K / 4); i += 256) {
            int r = i >> 5;
            int c = i & 31;
            int gr = block_row + r;
            float4 v = make_float4(0.f, 0.f, 0.f, 0.f);
            if (gr < M) v = X4[(size_t)gr * (K / 4) + c];
            Xs4[r * (XS / 4) + c] = v;
        }
    }
    __syncthreads();

    const int tx = tid & 15;
    const int ty = tid >> 4;

    float acc[8][TN];
#pragma unroll
    for (int i = 0; i < 8; i++)
#pragma unroll
        for (int j = 0; j < TN; j++) acc[i][j] = 0.f;

    const float4* Ws4 = (const float4*)Ws;
#pragma unroll 4
    for (int k = 0; k < K; k++) {
        float xr[8];
#pragma unroll
        for (int i = 0; i < 8; i++) xr[i] = Xs[(ty * 8 + i) * XS + k];
        float4 w[TN / 4];
#pragma unroll
        for (int j = 0; j < TN / 4; j++)
            w[j] = Ws4[k * (BN / 4) + tx * (TN / 4) + j];
#pragma unroll
        for (int i = 0; i < 8; i++) {
#pragma unroll
            for (int j = 0; j < TN / 4; j++) {
                acc[i][4 * j + 0] += xr[i] * w[j].x;
                acc[i][4 * j + 1] += xr[i] * w[j].y;
                acc[i][4 * j + 2] += xr[i] * w[j].z;
                acc[i][4 * j + 3] += xr[i] * w[j].w;
            }
        }
    }

#pragma unroll
    for (int i = 0; i < 8; i++) {
        int row = block_row + ty * 8 + i;
        if (row < M) {
            float dv = dinv[row];
#pragma unroll
            for (int j = 0; j < TN / 4; j++) {
                float4 o;
                o.x = acc[i][4 * j + 0] * dv;
                o.y = acc[i][4 * j + 1] * dv;
                o.z = acc[i][4 * j + 2] * dv;
                o.w = acc[i][4 * j + 3] * dv;
                ((float4*)out)[(size_t)row * (BN / 4) + tx * (TN / 4) + j] = o;
            }
        }
    }
}

// -------------------------------------------------- gather + fused epilogue
// 128 channels: warp per dst, lane holds float4 (4 channels).
__global__ void gather128_kernel(const float* __restrict__ A,
                                 const int* __restrict__ row_start,
                                 const int* __restrict__ csr_src,
                                 const float* __restrict__ dinv,
                                 const float* __restrict__ bias,
                                 float* __restrict__ out, int N) {
    int idx  = blockIdx.x * blockDim.x + threadIdx.x;
    int d    = idx >> 5;
    int lane = idx & 31;
    if (d >= N) return;
    const float4* A4 = (const float4*)A;
    float4 acc = A4[(size_t)d * 32 + lane];          // self loop
    int rs = row_start[d], re = row_start[d + 1];
    int j = rs;
    for (; j + 1 < re; j += 2) {
        int s0 = csr_src[j], s1 = csr_src[j + 1];
        float4 v0 = A4[(size_t)s0 * 32 + lane];
        float4 v1 = A4[(size_t)s1 * 32 + lane];
        acc.x += v0.x; acc.y += v0.y; acc.z += v0.z; acc.w += v0.w;
        acc.x += v1.x; acc.y += v1.y; acc.z += v1.z; acc.w += v1.w;
    }
    if (j < re) {
        float4 v = A4[(size_t)csr_src[j] * 32 + lane];
        acc.x += v.x; acc.y += v.y; acc.z += v.z; acc.w += v.w;
    }
    float  dv = dinv[d];
    float4 b  = ((const float4*)bias)[lane];
    float4 o;
    o.x = fmaxf(fmaf(acc.x, dv, b.x), 0.f);
    o.y = fmaxf(fmaf(acc.y, dv, b.y), 0.f);
    o.z = fmaxf(fmaf(acc.z, dv, b.z), 0.f);
    o.w = fmaxf(fmaf(acc.w, dv, b.w), 0.f);
    ((float4*)out)[(size_t)d * 32 + lane] = o;
}

// 64 channels: warp per dst, lane holds float2.
__global__ void gather64_kernel(const float* __restrict__ A,
                                const int* __restrict__ row_start,
                                const int* __restrict__ csr_src,
                                const float* __restrict__ dinv,
                                const float* __restrict__ bias,
                                float* __restrict__ out, int N) {
    int idx  = blockIdx.x * blockDim.x + threadIdx.x;
    int d    = idx >> 5;
    int lane = idx & 31;
    if (d >= N) return;
    const float2* A2 = (const float2*)A;
    float2 acc = A2[(size_t)d * 32 + lane];          // self loop
    int rs = row_start[d], re = row_start[d + 1];
    int j = rs;
    for (; j + 1 < re; j += 2) {
        int s0 = csr_src[j], s1 = csr_src[j + 1];
        float2 v0 = A2[(size_t)s0 * 32 + lane];
        float2 v1 = A2[(size_t)s1 * 32 + lane];
        acc.x += v0.x; acc.y += v0.y;
        acc.x += v1.x; acc.y += v1.y;
    }
    if (j < re) {
        float2 v = A2[(size_t)csr_src[j] * 32 + lane];
        acc.x += v.x; acc.y += v.y;
    }
    float  dv = dinv[d];
    float2 b  = ((const float2*)bias)[lane];
    float2 o;
    o.x = fmaxf(fmaf(acc.x, dv, b.x), 0.f);
    o.y = fmaxf(fmaf(acc.y, dv, b.y), 0.f);
    ((float2*)out)[(size_t)d * 32 + lane] = o;
}

// -------------------------------------------------------------------- launch
extern "C" void kernel_launch(void* const* d_in, const int* in_sizes, int n_in,
                              void* d_out, int out_size) {
    const float* x   = (const float*)d_in[0];
    const int*   ei  = (const int*)d_in[1];     // int32 (JAX x64 disabled)
    const float* W1  = (const float*)d_in[2];
    const float* b1  = (const float*)d_in[3];
    const float* W2  = (const float*)d_in[4];
    const float* b2  = (const float*)d_in[5];
    float*       out = (float*)d_out;

    const int N = in_sizes[0] / 128;
    const int E = in_sizes[1] / 2;
    const int* esrc = ei;
    const int* edst = ei + E;

    float *bufA, *bufB, *dinv;
    int *degc, *rows, *curs, *csr, *bsum, *boff;
    cudaGetSymbolAddress((void**)&bufA, g_bufA);
    cudaGetSymbolAddress((void**)&bufB, g_bufB);
    cudaGetSymbolAddress((void**)&dinv, g_dinv);
    cudaGetSymbolAddress((void**)&degc, g_degc);
    cudaGetSymbolAddress((void**)&rows, g_rows);
    cudaGetSymbolAddress((void**)&curs, g_curs);
    cudaGetSymbolAddress((void**)&csr,  g_csr);
    cudaGetSymbolAddress((void**)&bsum, g_bsum);
    cudaGetSymbolAddress((void**)&boff, g_boff);

    constexpr int SMEM1 = (128 * 132 + 128 * 128) * 4;  // 133120
    constexpr int SMEM2 = (128 * 132 + 128 * 64) * 4;   // 100352
    cudaFuncSetAttribute(gemm_scale_kernel<128>,
                         cudaFuncAttributeMaxDynamicSharedMemorySize, SMEM1);
    cudaFuncSetAttribute(gemm_scale_kernel<64>,
                         cudaFuncAttributeMaxDynamicSharedMemorySize, SMEM2);

    const int NB = (N + 1023) / 1024;   // scan blocks (98)

    // ---- CSR build (reused by both layers) + dinv
    zero_int_kernel<<<(N + 255) / 256, 256>>>(degc, N);
    count_kernel<<<(E + 255) / 256, 256>>>(edst, degc, E);
    dinv_kernel<<<(N + 255) / 256, 256>>>(degc, dinv, N);
    scan_local_kernel<<<NB, 1024>>>(degc, rows, bsum, N);
    scan_block_kernel<<<1, 128>>>(bsum, boff, rows, NB, N);
    scan_add_kernel<<<NB, 1024>>>(rows, curs, boff, N);
    place_kernel<<<(E + 255) / 256, 256>>>(esrc, edst, curs, csr, E);

    // ---- layer 1
    gemm_scale_kernel<128><<<(N + 127) / 128, 256, SMEM1>>>(x, W1, dinv, bufA, N);
    {
        long long t = (long long)N * 32;
        gather128_kernel<<<(unsigned)((t + 255) / 256), 256>>>(bufA, rows, csr, dinv, b1, bufB, N);
    }

    // ---- layer 2
    gemm_scale_kernel<64><<<(N + 127) / 128, 256, SMEM2>>>(bufB, W2, dinv, bufA, N);
    {
        long long t = (long long)N * 32;
        gather64_kernel<<<(unsigned)((t + 255) / 256), 256>>>(bufA, rows, csr, dinv, b2, out, N);
    }
}

// round 9
// speedup vs baseline: 3.7324x; 1.0061x over previous
#include <cuda_runtime.h>
#include <cuda_bf16.h>
#include <cstdint>

// ---------------------------------------------------------------------------
// 2-layer GCN, CSR-by-dst gather formulation:
//   deg[i] = 1 + in_degree(i);  dinv = rsqrt(deg)
//   h' = dinv ⊙ (X @ W)            (tf32x3 tensor-core GEMM, scaled write)
//   out[d] = relu(dinv[d] * (h'[d] + sum_{s in nbr(d)} h'[s]) + b)   (gather)
// CSR built once per call (counting sort, multi-block scan), reused by both
// layers.  GEMM uses mma.sync m16n8k8 tf32 with hi/lo operand splitting
// (3 passes) for fp32-class accuracy at tensor-core rate.
// ---------------------------------------------------------------------------

#define NN 100000
#define NE 1600000

__device__ __align__(128) float g_bufA[(size_t)NN * 128];
__device__ __align__(128) float g_bufB[(size_t)NN * 128];
__device__ __align__(128) float g_dinv[NN];
__device__ __align__(128) int   g_degc[NN];
__device__ __align__(128) int   g_rows[NN + 1];
__device__ __align__(128) int   g_curs[NN];
__device__ __align__(128) int   g_csr [NE];
__device__ __align__(128) int   g_bsum[256];   // per-block totals (<=98 used)
__device__ __align__(128) int   g_boff[256];   // exclusive block offsets

// ------------------------------------------------------------------ CSR build
__global__ void zero_int_kernel(int* __restrict__ p, int n) {
    int i = blockIdx.x * blockDim.x + threadIdx.x;
    if (i < n) p[i] = 0;
}

__global__ void count_kernel(const int* __restrict__ dst, int* __restrict__ cnt, int e) {
    int i = blockIdx.x * blockDim.x + threadIdx.x;
    if (i < e) atomicAdd(&cnt[dst[i]], 1);
}

__global__ void dinv_kernel(const int* __restrict__ cnt, float* __restrict__ dinv, int n) {
    int i = blockIdx.x * blockDim.x + threadIdx.x;
    if (i < n) dinv[i] = rsqrtf((float)(1 + cnt[i]));
}

__global__ __launch_bounds__(1024)
void scan_local_kernel(const int* __restrict__ deg, int* __restrict__ row_start,
                       int* __restrict__ bsum, int n) {
    __shared__ int wsum[32];
    const int tid = threadIdx.x, lane = tid & 31, wid = tid >> 5;
    const int i = blockIdx.x * 1024 + tid;
    int v = (i < n) ? deg[i] : 0;
    int x = v;
#pragma unroll
    for (int d = 1; d < 32; d <<= 1) {
        int y = __shfl_up_sync(0xffffffffu, x, d);
        if (lane >= d) x += y;
    }
    if (lane == 31) wsum[wid] = x;
    __syncthreads();
    if (wid == 0) {
        int s = wsum[lane];
#pragma unroll
        for (int d = 1; d < 32; d <<= 1) {
            int y = __shfl_up_sync(0xffffffffu, s, d);
            if (lane >= d) s += y;
        }
        wsum[lane] = s;
    }
    __syncthreads();
    int excl = (x - v) + (wid > 0 ? wsum[wid - 1] : 0);
    if (i < n) row_start[i] = excl;
    if (tid == 1023) bsum[blockIdx.x] = excl + v;
}

__global__ __launch_bounds__(128)
void scan_block_kernel(const int* __restrict__ bsum, int* __restrict__ boff,
                       int* __restrict__ row_start, int nb, int n) {
    __shared__ int carry_s;
    const int tid = threadIdx.x, lane = tid & 31;
    if (tid == 0) carry_s = 0;
    __syncthreads();
    for (int base = 0; base < nb; base += 32) {
        if (tid < 32) {
            int j = base + lane;
            int v = (j < nb) ? bsum[j] : 0;
            int x = v;
#pragma unroll
            for (int d = 1; d < 32; d <<= 1) {
                int y = __shfl_up_sync(0xffffffffu, x, d);
                if (lane >= d) x += y;
            }
            int carry = carry_s;
            if (j < nb) boff[j] = carry + (x - v);
            if (lane == 31) carry_s = carry + x;
        }
        __syncthreads();
    }
    if (tid == 0) row_start[n] = carry_s;
}

__global__ __launch_bounds__(1024)
void scan_add_kernel(int* __restrict__ row_start, int* __restrict__ cursor,
                     const int* __restrict__ boff, int n) {
    int i = blockIdx.x * 1024 + threadIdx.x;
    if (i < n) {
        int v = row_start[i] + boff[blockIdx.x];
        row_start[i] = v;
        cursor[i]    = v;
    }
}

__global__ void place_kernel(const int* __restrict__ src, const int* __restrict__ dst,
                             int* __restrict__ cursor, int* __restrict__ csr_src, int e) {
    int i = blockIdx.x * blockDim.x + threadIdx.x;
    if (i < e) {
        int pos = atomicAdd(&cursor[dst[i]], 1);
        csr_src[pos] = src[i];
    }
}

// ------------------------------------------------------------ tf32x3 GEMM
// out[m][c] = dinv[m] * sum_k X[m][k] * W[k][c]
// Split each operand v = hi + lo (tf32 each); accumulate ah*bh + ah*bl + al*bh
// in fp32 via mma.sync m16n8k8 -> fp32-class accuracy at tensor rate.
// BM=64, K=128. 256 threads = 8 warps as 2(m) x 4(n); warp tile 32 x (BN/4).

__device__ __forceinline__ float to_tf32(float x) {
    uint32_t u;
    asm("cvt.rna.tf32.f32 %0, %1;" : "=r"(u) : "f"(x));
    return __uint_as_float(u);
}

#define MMA_TF32(acc, a, b)                                                   \
    asm volatile(                                                             \
        "mma.sync.aligned.m16n8k8.row.col.f32.tf32.tf32.f32 "                 \
        "{%0,%1,%2,%3}, {%4,%5,%6,%7}, {%8,%9}, {%0,%1,%2,%3};"               \
        : "+f"((acc)[0]), "+f"((acc)[1]), "+f"((acc)[2]), "+f"((acc)[3])      \
        : "r"((a)[0]), "r"((a)[1]), "r"((a)[2]), "r"((a)[3]),                 \
          "r"((b)[0]), "r"((b)[1]))

template <int BN>
__global__ __launch_bounds__(256)
void gemm_tf32_kernel(const float* __restrict__ X, const float* __restrict__ W,
                      const float* __restrict__ dinv,
                      float* __restrict__ out, int M) {
    constexpr int K  = 128;
    constexpr int BM = 64;
    constexpr int LD = 132;          // smem row stride (floats): banks 4g+c, conflict-free
    constexpr int NT = BN / 32;      // n8-tiles per warp (4 or 2)

    extern __shared__ float smem[];
    float* Xh = smem;                // [BM][LD]
    float* Xl = Xh + BM * LD;
    float* Wh = Xl + BM * LD;        // [BN][LD]  (transposed: n-major)
    float* Wl = Wh + BN * LD;

    const int tid       = threadIdx.x;
    const int block_row = blockIdx.x * BM;

    // stage X tile, split hi/lo
    for (int i = tid; i < BM * (K / 4); i += 256) {
        int r = i >> 5, c4 = i & 31;
        int gr = block_row + r;
        float4 v = make_float4(0.f, 0.f, 0.f, 0.f);
        if (gr < M) v = ((const float4*)X)[(size_t)gr * 32 + c4];
        float4 h, l;
        h.x = to_tf32(v.x); l.x = to_tf32(v.x - h.x);
        h.y = to_tf32(v.y); l.y = to_tf32(v.y - h.y);
        h.z = to_tf32(v.z); l.z = to_tf32(v.z - h.z);
        h.w = to_tf32(v.w); l.w = to_tf32(v.w - h.w);
        *(float4*)&Xh[r * LD + 4 * c4] = h;
        *(float4*)&Xl[r * LD + 4 * c4] = l;
    }
    // stage W transposed (n-major), split hi/lo
    for (int i = tid; i < K * BN; i += 256) {
        int k = i / BN, n = i % BN;      // consecutive tid -> consecutive n: coalesced LDG
        float v = W[i];
        float h = to_tf32(v), l = to_tf32(v - h);
        Wh[n * LD + k] = h;
        Wl[n * LD + k] = l;
    }
    __syncthreads();

    const int lane = tid & 31, wid = tid >> 5;
    const int wm = wid & 1, wn = wid >> 1;
    const int m_base = wm * 32;
    const int n_base = wn * (BN / 4);
    const int g = lane >> 2, c = lane & 3;

    float acc[2][NT][4];
#pragma unroll
    for (int mt = 0; mt < 2; mt++)
#pragma unroll
        for (int nt = 0; nt < NT; nt++)
#pragma unroll
            for (int r = 0; r < 4; r++) acc[mt][nt][r] = 0.f;

#pragma unroll
    for (int ks = 0; ks < K; ks += 8) {
        uint32_t ah[2][4], al[2][4];
#pragma unroll
        for (int mt = 0; mt < 2; mt++) {
            const float* ph = &Xh[(m_base + mt * 16 + g) * LD + ks + c];
            const float* pl = &Xl[(m_base + mt * 16 + g) * LD + ks + c];
            ah[mt][0] = __float_as_uint(ph[0]);
            ah[mt][1] = __float_as_uint(ph[8 * LD]);
            ah[mt][2] = __float_as_uint(ph[4]);
            ah[mt][3] = __float_as_uint(ph[8 * LD + 4]);
            al[mt][0] = __float_as_uint(pl[0]);
            al[mt][1] = __float_as_uint(pl[8 * LD]);
            al[mt][2] = __float_as_uint(pl[4]);
            al[mt][3] = __float_as_uint(pl[8 * LD + 4]);
        }
        uint32_t bh[NT][2], bl[NT][2];
#pragma unroll
        for (int nt = 0; nt < NT; nt++) {
            const float* qh = &Wh[(n_base + nt * 8 + g) * LD + ks + c];
            const float* ql = &Wl[(n_base + nt * 8 + g) * LD + ks + c];
            bh[nt][0] = __float_as_uint(qh[0]);
            bh[nt][1] = __float_as_uint(qh[4]);
            bl[nt][0] = __float_as_uint(ql[0]);
            bl[nt][1] = __float_as_uint(ql[4]);
        }
#pragma unroll
        for (int mt = 0; mt < 2; mt++)
#pragma unroll
            for (int nt = 0; nt < NT; nt++) {
                MMA_TF32(acc[mt][nt], ah[mt], bh[nt]);
                MMA_TF32(acc[mt][nt], ah[mt], bl[nt]);
                MMA_TF32(acc[mt][nt], al[mt], bh[nt]);
            }
    }

    // epilogue: scale by dinv[row], store float2 pairs
#pragma unroll
    for (int mt = 0; mt < 2; mt++) {
        int row0 = block_row + m_base + mt * 16 + g;
        int row1 = row0 + 8;
        float dv0 = (row0 < M) ? dinv[row0] : 0.f;
        float dv1 = (row1 < M) ? dinv[row1] : 0.f;
#pragma unroll
        for (int nt = 0; nt < NT; nt++) {
            int col = n_base + nt * 8 + 2 * c;
            if (row0 < M) {
                float2 o = make_float2(acc[mt][nt][0] * dv0, acc[mt][nt][1] * dv0);
                *(float2*)&out[(size_t)row0 * BN + col] = o;
            }
            if (row1 < M) {
                float2 o = make_float2(acc[mt][nt][2] * dv1, acc[mt][nt][3] * dv1);
                *(float2*)&out[(size_t)row1 * BN + col] = o;
            }
        }
    }
}

// -------------------------------------------------- gather + fused epilogue
__global__ void gather128_kernel(const float* __restrict__ A,
                                 const int* __restrict__ row_start,
                                 const int* __restrict__ csr_src,
                                 const float* __restrict__ dinv,
                                 const float* __restrict__ bias,
                                 float* __restrict__ out, int N) {
    int idx  = blockIdx.x * blockDim.x + threadIdx.x;
    int d    = idx >> 5;
    int lane = idx & 31;
    if (d >= N) return;
    const float4* A4 = (const float4*)A;
    float4 acc = A4[(size_t)d * 32 + lane];          // self loop
    int rs = row_start[d], re = row_start[d + 1];
    int j = rs;
    for (; j + 1 < re; j += 2) {
        int s0 = csr_src[j], s1 = csr_src[j + 1];
        float4 v0 = A4[(size_t)s0 * 32 + lane];
        float4 v1 = A4[(size_t)s1 * 32 + lane];
        acc.x += v0.x; acc.y += v0.y; acc.z += v0.z; acc.w += v0.w;
        acc.x += v1.x; acc.y += v1.y; acc.z += v1.z; acc.w += v1.w;
    }
    if (j < re) {
        float4 v = A4[(size_t)csr_src[j] * 32 + lane];
        acc.x += v.x; acc.y += v.y; acc.z += v.z; acc.w += v.w;
    }
    float  dv = dinv[d];
    float4 b  = ((const float4*)bias)[lane];
    float4 o;
    o.x = fmaxf(fmaf(acc.x, dv, b.x), 0.f);
    o.y = fmaxf(fmaf(acc.y, dv, b.y), 0.f);
    o.z = fmaxf(fmaf(acc.z, dv, b.z), 0.f);
    o.w = fmaxf(fmaf(acc.w, dv, b.w), 0.f);
    ((float4*)out)[(size_t)d * 32 + lane] = o;
}

__global__ void gather64_kernel(const float* __restrict__ A,
                                const int* __restrict__ row_start,
                                const int* __restrict__ csr_src,
                                const float* __restrict__ dinv,
                                const float* __restrict__ bias,
                                float* __restrict__ out, int N) {
    int idx  = blockIdx.x * blockDim.x + threadIdx.x;
    int d    = idx >> 5;
    int lane = idx & 31;
    if (d >= N) return;
    const float2* A2 = (const float2*)A;
    float2 acc = A2[(size_t)d * 32 + lane];          // self loop
    int rs = row_start[d], re = row_start[d + 1];
    int j = rs;
    for (; j + 1 < re; j += 2) {
        int s0 = csr_src[j], s1 = csr_src[j + 1];
        float2 v0 = A2[(size_t)s0 * 32 + lane];
        float2 v1 = A2[(size_t)s1 * 32 + lane];
        acc.x += v0.x; acc.y += v0.y;
        acc.x += v1.x; acc.y += v1.y;
    }
    if (j < re) {
        float2 v = A2[(size_t)csr_src[j] * 32 + lane];
        acc.x += v.x; acc.y += v.y;
    }
    float  dv = dinv[d];
    float2 b  = ((const float2*)bias)[lane];
    float2 o;
    o.x = fmaxf(fmaf(acc.x, dv, b.x), 0.f);
    o.y = fmaxf(fmaf(acc.y, dv, b.y), 0.f);
    ((float2*)out)[(size_t)d * 32 + lane] = o;
}

// -------------------------------------------------------------------- launch
extern "C" void kernel_launch(void* const* d_in, const int* in_sizes, int n_in,
                              void* d_out, int out_size) {
    const float* x   = (const float*)d_in[0];
    const int*   ei  = (const int*)d_in[1];     // int32 (JAX x64 disabled)
    const float* W1  = (const float*)d_in[2];
    const float* b1  = (const float*)d_in[3];
    const float* W2  = (const float*)d_in[4];
    const float* b2  = (const float*)d_in[5];
    float*       out = (float*)d_out;

    const int N = in_sizes[0] / 128;
    const int E = in_sizes[1] / 2;
    const int* esrc = ei;
    const int* edst = ei + E;

    float *bufA, *bufB, *dinv;
    int *degc, *rows, *curs, *csr, *bsum, *boff;
    cudaGetSymbolAddress((void**)&bufA, g_bufA);
    cudaGetSymbolAddress((void**)&bufB, g_bufB);
    cudaGetSymbolAddress((void**)&dinv, g_dinv);
    cudaGetSymbolAddress((void**)&degc, g_degc);
    cudaGetSymbolAddress((void**)&rows, g_rows);
    cudaGetSymbolAddress((void**)&curs, g_curs);
    cudaGetSymbolAddress((void**)&csr,  g_csr);
    cudaGetSymbolAddress((void**)&bsum, g_bsum);
    cudaGetSymbolAddress((void**)&boff, g_boff);

    constexpr int SMEM1 = (2 * 64 + 2 * 128) * 132 * 4;  // 202752
    constexpr int SMEM2 = (2 * 64 + 2 * 64)  * 132 * 4;  // 135168
    cudaFuncSetAttribute(gemm_tf32_kernel<128>,
                         cudaFuncAttributeMaxDynamicSharedMemorySize, SMEM1);
    cudaFuncSetAttribute(gemm_tf32_kernel<64>,
                         cudaFuncAttributeMaxDynamicSharedMemorySize, SMEM2);

    const int NB = (N + 1023) / 1024;   // scan blocks (98)

    // ---- CSR build (reused by both layers) + dinv
    zero_int_kernel<<<(N + 255) / 256, 256>>>(degc, N);
    count_kernel<<<(E + 255) / 256, 256>>>(edst, degc, E);
    dinv_kernel<<<(N + 255) / 256, 256>>>(degc, dinv, N);
    scan_local_kernel<<<NB, 1024>>>(degc, rows, bsum, N);
    scan_block_kernel<<<1, 128>>>(bsum, boff, rows, NB, N);
    scan_add_kernel<<<NB, 1024>>>(rows, curs, boff, N);
    place_kernel<<<(E + 255) / 256, 256>>>(esrc, edst, curs, csr, E);

    // ---- layer 1
    gemm_tf32_kernel<128><<<(N + 63) / 64, 256, SMEM1>>>(x, W1, dinv, bufA, N);
    {
        long long t = (long long)N * 32;
        gather128_kernel<<<(unsigned)((t + 255) / 256), 256>>>(bufA, rows, csr, dinv, b1, bufB, N);
    }

    // ---- layer 2
    gemm_tf32_kernel<64><<<(N + 63) / 64, 256, SMEM2>>>(bufB, W2, dinv, bufA, N);
    {
        long long t = (long long)N * 32;
        gather64_kernel<<<(unsigned)((t + 255) / 256), 256>>>(bufA, rows, csr, dinv, b2, out, N);
    }
}